// round 3
// baseline (speedup 1.0000x reference)
#include <cuda_runtime.h>
#include <math.h>

#define NB 2
#define LQ 2048
#define SQ 2048
#define HH 8
#define EE 64
#define DD 64
#define CC 256
#define KK 32
#define NH (NB*HH)
#define TEMP 0.125f

// ---------------- scratch (device globals; no allocation allowed) ----------
__device__ float g_Qg[NH*CC*EE];        // per-cluster mean queries
__device__ float g_cnt[NH*CC];          // cluster counts
__device__ float g_probs[NH*CC*SQ];     // scores, then softmax probs (topk zeroed)
__device__ float g_Vbtm[NH*CC*DD];      // bottom-k weighted V per cluster
__device__ float g_Ab[NH*CC];           // top-k probability mass (= 1 - A_bottomk)
__device__ int   g_topk[NH*CC*KK];      // top-k key indices per cluster

// ---------------- zero scratch ---------------------------------------------
__global__ void k_zero() {
    int i = blockIdx.x * blockDim.x + threadIdx.x;
    if (i < NH*CC*EE) { g_Qg[i] = 0.f; g_Vbtm[i] = 0.f; }
    if (i < NH*CC)    g_cnt[i] = 0.f;
}

// ---------------- cluster sums via atomics ----------------------------------
__global__ void k_qsum(const float* __restrict__ q, const int* __restrict__ cid) {
    int t = blockIdx.x * blockDim.x + threadIdx.x;   // NB*HH*LQ*16 threads
    if (t >= NB*HH*LQ*16) return;
    int e4  = t & 15;
    int nhl = t >> 4;
    int l = nhl % LQ;
    int h = (nhl / LQ) % HH;
    int n = nhl / (LQ*HH);
    int c = __ldg(&cid[(n*HH + h)*LQ + l]);
    const float4 v = *(const float4*)(q + (size_t)((n*LQ + l)*HH + h)*EE + e4*4);
    float* dst = g_Qg + ((n*HH + h)*CC + c)*EE + e4*4;
    atomicAdd(dst + 0, v.x);
    atomicAdd(dst + 1, v.y);
    atomicAdd(dst + 2, v.z);
    atomicAdd(dst + 3, v.w);
    if (e4 == 0) atomicAdd(&g_cnt[(n*HH + h)*CC + c], 1.f);
}

// ---------------- divide by counts ------------------------------------------
__global__ void k_qmean() {
    int i = blockIdx.x * blockDim.x + threadIdx.x;
    if (i >= NH*CC*EE) return;
    g_Qg[i] /= fmaxf(g_cnt[i >> 6], 1.f);
}

// ---------------- QK GEMM: scores[nh][c][s] = Qg[c]·K[s] --------------------
// grid (S/64, C/64, NH), 256 threads, 64x64 tile, K-dim = E = 64 (one tile)
__global__ void k_qk(const float* __restrict__ keys) {
    __shared__ float shQ[64][65];
    __shared__ float shK[64][65];
    const int nh = blockIdx.z, n = nh >> 3, h = nh & 7;
    const int c0 = blockIdx.y * 64, s0 = blockIdx.x * 64;
    const int t = threadIdx.x;

    const float* Qb = g_Qg + (nh*CC + c0)*EE;
    #pragma unroll
    for (int r = 0; r < 4; r++) {
        int lin = t + r*256, row = lin >> 4, c4 = lin & 15;
        float4 v = *(const float4*)(Qb + row*EE + c4*4);
        shQ[row][c4*4+0] = v.x; shQ[row][c4*4+1] = v.y;
        shQ[row][c4*4+2] = v.z; shQ[row][c4*4+3] = v.w;
    }
    #pragma unroll
    for (int r = 0; r < 4; r++) {
        int lin = t + r*256, row = lin >> 4, c4 = lin & 15;
        float4 v = *(const float4*)(keys + (size_t)((n*SQ + s0 + row)*HH + h)*EE + c4*4);
        shK[row][c4*4+0] = v.x; shK[row][c4*4+1] = v.y;
        shK[row][c4*4+2] = v.z; shK[row][c4*4+3] = v.w;
    }
    __syncthreads();

    const int tc = t >> 4, ts = t & 15;
    float acc[4][4];
    #pragma unroll
    for (int i = 0; i < 4; i++)
        #pragma unroll
        for (int j = 0; j < 4; j++) acc[i][j] = 0.f;

    #pragma unroll 8
    for (int e = 0; e < 64; e++) {
        float a[4], b[4];
        #pragma unroll
        for (int i = 0; i < 4; i++) a[i] = shQ[tc*4 + i][e];
        #pragma unroll
        for (int j = 0; j < 4; j++) b[j] = shK[ts*4 + j][e];
        #pragma unroll
        for (int i = 0; i < 4; i++)
            #pragma unroll
            for (int j = 0; j < 4; j++) acc[i][j] += a[i]*b[j];
    }
    #pragma unroll
    for (int i = 0; i < 4; i++) {
        float* dst = g_probs + (size_t)(nh*CC + c0 + tc*4 + i)*SQ + s0 + ts*4;
        #pragma unroll
        for (int j = 0; j < 4; j++) dst[j] = acc[i][j];
    }
}

// ---------------- softmax stats + top-32 per cluster row --------------------
// one block (256 threads) per (nh, c) row of 2048 scores
__global__ void k_stats() {
    __shared__ float sh[SQ];
    __shared__ float rv[8];
    __shared__ int   ri[8];
    __shared__ float s_bc;
    const int row = blockIdx.x;
    const int t = threadIdx.x;
    float* P = g_probs + (size_t)row * SQ;

    // load logits, row max
    float lmax = -INFINITY;
    #pragma unroll
    for (int j = 0; j < 8; j++) {
        float v = TEMP * P[t + j*256];
        sh[t + j*256] = v;
        lmax = fmaxf(lmax, v);
    }
    #pragma unroll
    for (int o = 16; o; o >>= 1) lmax = fmaxf(lmax, __shfl_xor_sync(~0u, lmax, o));
    if ((t & 31) == 0) rv[t >> 5] = lmax;
    __syncthreads();
    if (t == 0) {
        float m = rv[0];
        #pragma unroll
        for (int w = 1; w < 8; w++) m = fmaxf(m, rv[w]);
        s_bc = m;
    }
    __syncthreads();
    const float M = s_bc;

    // denominator
    float lsum = 0.f;
    #pragma unroll
    for (int j = 0; j < 8; j++) lsum += __expf(sh[t + j*256] - M);
    #pragma unroll
    for (int o = 16; o; o >>= 1) lsum += __shfl_xor_sync(~0u, lsum, o);
    if ((t & 31) == 0) rv[t >> 5] = lsum;
    __syncthreads();
    if (t == 0) {
        float z = 0.f;
        #pragma unroll
        for (int w = 0; w < 8; w++) z += rv[w];
        s_bc = 1.f / z;
    }
    __syncthreads();
    const float invZ = s_bc;

    // write normalized probs
    #pragma unroll
    for (int j = 0; j < 8; j++) P[t + j*256] = __expf(sh[t + j*256] - M) * invZ;

    // iterative top-32 argmax (stable: lower index wins ties, matching lax.top_k)
    float psum = 0.f;
    for (int it = 0; it < KK; it++) {
        float bv = -INFINITY; int bi = 0x7fffffff;
        #pragma unroll
        for (int j = 0; j < 8; j++) {
            int idx = t + j*256;
            float v = sh[idx];
            if (v > bv || (v == bv && idx < bi)) { bv = v; bi = idx; }
        }
        #pragma unroll
        for (int o = 16; o; o >>= 1) {
            float ov = __shfl_xor_sync(~0u, bv, o);
            int   oi = __shfl_xor_sync(~0u, bi, o);
            if (ov > bv || (ov == bv && oi < bi)) { bv = ov; bi = oi; }
        }
        if ((t & 31) == 0) { rv[t >> 5] = bv; ri[t >> 5] = bi; }
        __syncthreads();
        if (t == 0) {
            float Bv = rv[0]; int Bi = ri[0];
            #pragma unroll
            for (int w = 1; w < 8; w++)
                if (rv[w] > Bv || (rv[w] == Bv && ri[w] < Bi)) { Bv = rv[w]; Bi = ri[w]; }
            g_topk[row*KK + it] = Bi;
            psum += __expf(Bv - M) * invZ;
            sh[Bi] = -INFINITY;   // remove from future argmax
            P[Bi]  = 0.f;         // zero top-k prob (bottom-k mask)
        }
        __syncthreads();
    }
    if (t == 0) g_Ab[row] = psum;   // top-k probability mass = 1 - A_bottomk
}

// ---------------- V_btm = probs @ V (split-K, atomic accumulate) ------------
// grid (8 k-slices, C/64, NH), 256 threads; each slice covers 256 s positions
__global__ void k_vbtm(const float* __restrict__ values) {
    __shared__ float shP[64][33];
    __shared__ float shV[32][65];
    const int nh = blockIdx.z, n = nh >> 3, h = nh & 7;
    const int c0 = blockIdx.y * 64;
    const int sbase = blockIdx.x * 256;
    const int t = threadIdx.x;
    const int tc = t >> 4, ts = t & 15;

    float acc[4][4];
    #pragma unroll
    for (int i = 0; i < 4; i++)
        #pragma unroll
        for (int j = 0; j < 4; j++) acc[i][j] = 0.f;

    for (int ks = 0; ks < 8; ks++) {
        const int s0 = sbase + ks*32;
        // load P tile 64x32
        #pragma unroll
        for (int r = 0; r < 2; r++) {
            int lin = t + r*256, row = lin >> 3, c4 = lin & 7;
            float4 v = *(const float4*)(g_probs + (size_t)(nh*CC + c0 + row)*SQ + s0 + c4*4);
            shP[row][c4*4+0] = v.x; shP[row][c4*4+1] = v.y;
            shP[row][c4*4+2] = v.z; shP[row][c4*4+3] = v.w;
        }
        // load V tile 32x64
        #pragma unroll
        for (int r = 0; r < 2; r++) {
            int lin = t + r*256, row = lin >> 4, c4 = lin & 15;
            float4 v = *(const float4*)(values + (size_t)((n*SQ + s0 + row)*HH + h)*DD + c4*4);
            shV[row][c4*4+0] = v.x; shV[row][c4*4+1] = v.y;
            shV[row][c4*4+2] = v.z; shV[row][c4*4+3] = v.w;
        }
        __syncthreads();
        #pragma unroll 8
        for (int s = 0; s < 32; s++) {
            float a[4], b[4];
            #pragma unroll
            for (int i = 0; i < 4; i++) a[i] = shP[tc*4 + i][s];
            #pragma unroll
            for (int j = 0; j < 4; j++) b[j] = shV[s][ts*4 + j];
            #pragma unroll
            for (int i = 0; i < 4; i++)
                #pragma unroll
                for (int j = 0; j < 4; j++) acc[i][j] += a[i]*b[j];
        }
        __syncthreads();
    }
    #pragma unroll
    for (int i = 0; i < 4; i++) {
        float* dst = g_Vbtm + (nh*CC + c0 + tc*4 + i)*DD + ts*4;
        #pragma unroll
        for (int j = 0; j < 4; j++) atomicAdd(dst + j, acc[i][j]);
    }
}

// ---------------- per-query top-k attention + combine -----------------------
// one warp per query; phase 1: lane<->key, phase 2: lane<->d
__global__ void k_final(const float* __restrict__ q, const float* __restrict__ keys,
                        const float* __restrict__ values, const int* __restrict__ cid,
                        float* __restrict__ out) {
    __shared__ float wsh[16][32];
    __shared__ int   ish[16][32];
    const int wi   = threadIdx.x >> 5;
    const int lane = threadIdx.x & 31;
    const int w = blockIdx.x * 16 + wi;
    const int l = w % LQ;
    const int h = (w / LQ) % HH;
    const int n = w / (LQ*HH);
    const int nh = n*HH + h;
    const int c = __ldg(&cid[nh*LQ + l]);
    const int base = nh*CC + c;

    const int ki = g_topk[base*KK + lane];
    const float* qrow = q    + (size_t)((n*LQ + l)*HH + h)*EE;
    const float* krow = keys + (size_t)((n*SQ + ki)*HH + h)*EE;
    float dot = 0.f;
    #pragma unroll
    for (int e4 = 0; e4 < 16; e4++) {
        float4 qv = *(const float4*)(qrow + e4*4);
        float4 kv = *(const float4*)(krow + e4*4);
        dot += qv.x*kv.x + qv.y*kv.y + qv.z*kv.z + qv.w*kv.w;
    }
    float lg = TEMP * dot;
    float m = lg;
    #pragma unroll
    for (int o = 16; o; o >>= 1) m = fmaxf(m, __shfl_xor_sync(~0u, m, o));
    float p = __expf(lg - m);
    float z = p;
    #pragma unroll
    for (int o = 16; o; o >>= 1) z += __shfl_xor_sync(~0u, z, o);
    const float wk = p * (g_Ab[base] / z);   // scaled by top-k mass

    wsh[wi][lane] = wk;
    ish[wi][lane] = ki;
    __syncwarp();

    float acc0 = g_Vbtm[base*DD + lane];
    float acc1 = g_Vbtm[base*DD + lane + 32];
    #pragma unroll
    for (int k = 0; k < KK; k++) {
        float wv = wsh[wi][k];
        const float* vr = values + (size_t)((n*SQ + ish[wi][k])*HH + h)*DD;
        acc0 += wv * vr[lane];
        acc1 += wv * vr[lane + 32];
    }
    float* orow = out + (size_t)((n*LQ + l)*HH + h)*DD;
    orow[lane]      = acc0;
    orow[lane + 32] = acc1;
}

// ---------------- launch -----------------------------------------------------
extern "C" void kernel_launch(void* const* d_in, const int* in_sizes, int n_in,
                              void* d_out, int out_size) {
    const float* queries = (const float*)d_in[0];
    const float* keys    = (const float*)d_in[1];
    const float* values  = (const float*)d_in[2];
    const int*   cids    = (const int*)d_in[3];
    float* out = (float*)d_out;

    k_zero<<<(NH*CC*EE + 255)/256, 256>>>();
    k_qsum<<<(NB*HH*LQ*16 + 255)/256, 256>>>(queries, cids);
    k_qmean<<<(NH*CC*EE + 255)/256, 256>>>();

    dim3 gB(SQ/64, CC/64, NH);
    k_qk<<<gB, 256>>>(keys);

    k_stats<<<NH*CC, 256>>>();

    dim3 gD(8, CC/64, NH);
    k_vbtm<<<gD, 256>>>(values);

    k_final<<<NB*HH*LQ/16, 512>>>(queries, keys, values, cids, out);
}

// round 5
// speedup vs baseline: 1.1224x; 1.1224x over previous
#include <cuda_runtime.h>
#include <math.h>

#define NB 2
#define LQ 2048
#define SQ 2048
#define HH 8
#define EE 64
#define DD 64
#define CC 256
#define KK 32
#define NH (NB*HH)
#define TEMP 0.125f

// ---------------- scratch (device globals; no allocation allowed) ----------
__device__ float g_Qg[NH*CC*EE];        // per-cluster mean queries
__device__ int   g_qcnt[NH*CC];         // cluster counts (int)
__device__ float g_probs[NH*CC*SQ];     // scores, then softmax probs (topk zeroed)
__device__ float g_Vbtm[NH*CC*DD];      // bottom-k weighted V per cluster
__device__ float g_Ab[NH*CC];           // top-k probability mass (= 1 - A_bottomk)
__device__ int   g_topk[NH*CC*KK];      // top-k key indices per cluster
__device__ int   g_qoff[NH*CC + 1];     // query-list offsets per cluster
__device__ int   g_qcur[NH*CC];         // scatter cursors
__device__ int   g_qlist[NH*LQ];        // query l-indices grouped by cluster

// ---------------- zero scratch ---------------------------------------------
__global__ void k_zero() {
    int i = blockIdx.x * blockDim.x + threadIdx.x;
    if (i < NH*CC*EE) { g_Qg[i] = 0.f; g_Vbtm[i] = 0.f; }
    if (i < NH*CC)    g_qcnt[i] = 0;
}

// ---------------- cluster sums via atomics ----------------------------------
__global__ void k_qsum(const float* __restrict__ q, const int* __restrict__ cid) {
    int t = blockIdx.x * blockDim.x + threadIdx.x;   // NB*HH*LQ*16 threads
    if (t >= NB*HH*LQ*16) return;
    int e4  = t & 15;
    int nhl = t >> 4;
    int l = nhl % LQ;
    int h = (nhl / LQ) % HH;
    int n = nhl / (LQ*HH);
    int c = __ldg(&cid[(n*HH + h)*LQ + l]);
    const float4 v = *(const float4*)(q + (size_t)((n*LQ + l)*HH + h)*EE + e4*4);
    float* dst = g_Qg + ((n*HH + h)*CC + c)*EE + e4*4;
    atomicAdd(dst + 0, v.x);
    atomicAdd(dst + 1, v.y);
    atomicAdd(dst + 2, v.z);
    atomicAdd(dst + 3, v.w);
    if (e4 == 0) atomicAdd(&g_qcnt[(n*HH + h)*CC + c], 1);
}

// ---------------- divide by counts ------------------------------------------
__global__ void k_qmean() {
    int i = blockIdx.x * blockDim.x + threadIdx.x;
    if (i >= NH*CC*EE) return;
    g_Qg[i] /= fmaxf((float)g_qcnt[i >> 6], 1.f);
}

// ---------------- exclusive scan of 4096 counts (1 block, 1024 thr) ---------
__global__ void k_scan() {
    __shared__ int wsum[32];
    const int t = threadIdx.x, lane = t & 31, wid = t >> 5;
    int c0 = g_qcnt[t*4+0], c1 = g_qcnt[t*4+1], c2 = g_qcnt[t*4+2], c3 = g_qcnt[t*4+3];
    int tot = c0 + c1 + c2 + c3;
    int inc = tot;
    #pragma unroll
    for (int o = 1; o < 32; o <<= 1) {
        int x = __shfl_up_sync(~0u, inc, o);
        if (lane >= o) inc += x;
    }
    if (lane == 31) wsum[wid] = inc;
    __syncthreads();
    if (wid == 0) {
        int v = wsum[lane];
        #pragma unroll
        for (int o = 1; o < 32; o <<= 1) {
            int x = __shfl_up_sync(~0u, v, o);
            if (lane >= o) v += x;
        }
        wsum[lane] = v;
    }
    __syncthreads();
    int ex = (wid ? wsum[wid-1] : 0) + inc - tot;
    g_qoff[t*4+0] = ex; g_qcur[t*4+0] = ex; ex += c0;
    g_qoff[t*4+1] = ex; g_qcur[t*4+1] = ex; ex += c1;
    g_qoff[t*4+2] = ex; g_qcur[t*4+2] = ex; ex += c2;
    g_qoff[t*4+3] = ex; g_qcur[t*4+3] = ex; ex += c3;
    if (t == 1023) g_qoff[NH*CC] = ex;
}

// ---------------- scatter query indices into cluster-grouped lists ----------
__global__ void k_scatter(const int* __restrict__ cid) {
    int t = blockIdx.x * blockDim.x + threadIdx.x;   // NH*LQ threads
    if (t >= NH*LQ) return;
    int l  = t % LQ;
    int nh = t / LQ;
    int c  = __ldg(&cid[nh*LQ + l]);
    int pos = atomicAdd(&g_qcur[nh*CC + c], 1);
    g_qlist[pos] = l;
}

// ---------------- QK GEMM: scores[nh][c][s] = Qg[c]·K[s] --------------------
__global__ void k_qk(const float* __restrict__ keys) {
    __shared__ float shQ[64][65];
    __shared__ float shK[64][65];
    const int nh = blockIdx.z, n = nh >> 3, h = nh & 7;
    const int c0 = blockIdx.y * 64, s0 = blockIdx.x * 64;
    const int t = threadIdx.x;

    const float* Qb = g_Qg + (nh*CC + c0)*EE;
    #pragma unroll
    for (int r = 0; r < 4; r++) {
        int lin = t + r*256, row = lin >> 4, c4 = lin & 15;
        float4 v = *(const float4*)(Qb + row*EE + c4*4);
        shQ[row][c4*4+0] = v.x; shQ[row][c4*4+1] = v.y;
        shQ[row][c4*4+2] = v.z; shQ[row][c4*4+3] = v.w;
    }
    #pragma unroll
    for (int r = 0; r < 4; r++) {
        int lin = t + r*256, row = lin >> 4, c4 = lin & 15;
        float4 v = *(const float4*)(keys + (size_t)((n*SQ + s0 + row)*HH + h)*EE + c4*4);
        shK[row][c4*4+0] = v.x; shK[row][c4*4+1] = v.y;
        shK[row][c4*4+2] = v.z; shK[row][c4*4+3] = v.w;
    }
    __syncthreads();

    const int tc = t >> 4, ts = t & 15;
    float acc[4][4];
    #pragma unroll
    for (int i = 0; i < 4; i++)
        #pragma unroll
        for (int j = 0; j < 4; j++) acc[i][j] = 0.f;

    #pragma unroll 8
    for (int e = 0; e < 64; e++) {
        float a[4], b[4];
        #pragma unroll
        for (int i = 0; i < 4; i++) a[i] = shQ[tc*4 + i][e];
        #pragma unroll
        for (int j = 0; j < 4; j++) b[j] = shK[ts*4 + j][e];
        #pragma unroll
        for (int i = 0; i < 4; i++)
            #pragma unroll
            for (int j = 0; j < 4; j++) acc[i][j] += a[i]*b[j];
    }
    #pragma unroll
    for (int i = 0; i < 4; i++) {
        float* dst = g_probs + (size_t)(nh*CC + c0 + tc*4 + i)*SQ + s0 + ts*4;
        #pragma unroll
        for (int j = 0; j < 4; j++) dst[j] = acc[i][j];
    }
}

// ---------------- softmax + top-32 (register-resident) ----------------------
// one block (256 threads) per (nh, c) row of 2048 scores
__global__ void k_stats() {
    __shared__ float swv[8];
    __shared__ int   swi[8];
    const int row = blockIdx.x;
    const int t = threadIdx.x, lane = t & 31, wid = t >> 5;
    float* P = g_probs + (size_t)row * SQ;

    // load logits into registers, compute row max
    float v[8];
    float lmax = -INFINITY;
    #pragma unroll
    for (int j = 0; j < 8; j++) {
        v[j] = TEMP * P[t + j*256];
        lmax = fmaxf(lmax, v[j]);
    }
    #pragma unroll
    for (int o = 16; o; o >>= 1) lmax = fmaxf(lmax, __shfl_xor_sync(~0u, lmax, o));
    if (lane == 0) swv[wid] = lmax;
    __syncthreads();
    float M = swv[0];
    #pragma unroll
    for (int w = 1; w < 8; w++) M = fmaxf(M, swv[w]);
    __syncthreads();

    // denominator; cache exponentials for the prob-write
    float ex[8];
    float lsum = 0.f;
    #pragma unroll
    for (int j = 0; j < 8; j++) { ex[j] = __expf(v[j] - M); lsum += ex[j]; }
    #pragma unroll
    for (int o = 16; o; o >>= 1) lsum += __shfl_xor_sync(~0u, lsum, o);
    if (lane == 0) swv[wid] = lsum;
    __syncthreads();
    float Z = 0.f;
    #pragma unroll
    for (int w = 0; w < 8; w++) Z += swv[w];
    const float invZ = 1.f / Z;
    __syncthreads();

    // write normalized probs
    #pragma unroll
    for (int j = 0; j < 8; j++) P[t + j*256] = ex[j] * invZ;

    // iterative top-32: thread-local register argmax, warp shuffle, block scan
    float psum = 0.f;
    for (int it = 0; it < KK; it++) {
        float bv = -INFINITY; int bi = 0x7fffffff;
        #pragma unroll
        for (int j = 0; j < 8; j++) {
            // ascending j => ascending idx within thread; strict > keeps lowest idx
            if (v[j] > bv) { bv = v[j]; bi = t + j*256; }
        }
        #pragma unroll
        for (int o = 16; o; o >>= 1) {
            float ov = __shfl_xor_sync(~0u, bv, o);
            int   oi = __shfl_xor_sync(~0u, bi, o);
            if (ov > bv || (ov == bv && oi < bi)) { bv = ov; bi = oi; }
        }
        if (lane == 0) { swv[wid] = bv; swi[wid] = bi; }
        __syncthreads();
        float Bv = swv[0]; int Bi = swi[0];
        #pragma unroll
        for (int w = 1; w < 8; w++)
            if (swv[w] > Bv || (swv[w] == Bv && swi[w] < Bi)) { Bv = swv[w]; Bi = swi[w]; }
        psum += __expf(Bv - M);
        if (t == 0) g_topk[row*KK + it] = Bi;
        if ((Bi & 255) == t) {        // owner removes + zeroes prob
            v[Bi >> 8] = -INFINITY;
            P[Bi] = 0.f;
        }
        __syncthreads();
    }
    if (t == 0) g_Ab[row] = psum * invZ;   // top-k probability mass
}

// ---------------- V_btm = probs @ V (split-K, atomic accumulate) ------------
__global__ void k_vbtm(const float* __restrict__ values) {
    __shared__ float shP[64][33];
    __shared__ float shV[32][65];
    const int nh = blockIdx.z, n = nh >> 3, h = nh & 7;
    const int c0 = blockIdx.y * 64;
    const int sbase = blockIdx.x * 256;
    const int t = threadIdx.x;
    const int tc = t >> 4, ts = t & 15;

    float acc[4][4];
    #pragma unroll
    for (int i = 0; i < 4; i++)
        #pragma unroll
        for (int j = 0; j < 4; j++) acc[i][j] = 0.f;

    for (int ks = 0; ks < 8; ks++) {
        const int s0 = sbase + ks*32;
        #pragma unroll
        for (int r = 0; r < 2; r++) {
            int lin = t + r*256, row = lin >> 3, c4 = lin & 7;
            float4 v = *(const float4*)(g_probs + (size_t)(nh*CC + c0 + row)*SQ + s0 + c4*4);
            shP[row][c4*4+0] = v.x; shP[row][c4*4+1] = v.y;
            shP[row][c4*4+2] = v.z; shP[row][c4*4+3] = v.w;
        }
        #pragma unroll
        for (int r = 0; r < 2; r++) {
            int lin = t + r*256, row = lin >> 4, c4 = lin & 15;
            float4 v = *(const float4*)(values + (size_t)((n*SQ + s0 + row)*HH + h)*DD + c4*4);
            shV[row][c4*4+0] = v.x; shV[row][c4*4+1] = v.y;
            shV[row][c4*4+2] = v.z; shV[row][c4*4+3] = v.w;
        }
        __syncthreads();
        #pragma unroll 8
        for (int s = 0; s < 32; s++) {
            float a[4], b[4];
            #pragma unroll
            for (int i = 0; i < 4; i++) a[i] = shP[tc*4 + i][s];
            #pragma unroll
            for (int j = 0; j < 4; j++) b[j] = shV[s][ts*4 + j];
            #pragma unroll
            for (int i = 0; i < 4; i++)
                #pragma unroll
                for (int j = 0; j < 4; j++) acc[i][j] += a[i]*b[j];
        }
        __syncthreads();
    }
    #pragma unroll
    for (int i = 0; i < 4; i++) {
        float* dst = g_Vbtm + (nh*CC + c0 + tc*4 + i)*DD + ts*4;
        #pragma unroll
        for (int j = 0; j < 4; j++) atomicAdd(dst + j, acc[i][j]);
    }
}

// ---------------- per-cluster final attention --------------------------------
// one block per (nh, c): gather K_sel/V_sel once, serve all queries in cluster
__global__ void k_final2(const float* __restrict__ q, const float* __restrict__ keys,
                         const float* __restrict__ values, float* __restrict__ out) {
    __shared__ int   s_top[KK];
    __shared__ float Ksel[KK][65];
    __shared__ float Vsel[KK][65];
    const int b = blockIdx.x;            // nh*CC + c
    const int nh = b >> 8, n = nh >> 3, h = nh & 7;
    const int t = threadIdx.x, lane = t & 31, wi = t >> 5;

    const int q0 = g_qoff[b];
    const int q1 = g_qoff[b + 1];
    if (q0 == q1) return;                // empty cluster: nothing to emit

    if (t < KK) s_top[t] = g_topk[b*KK + t];
    __syncthreads();

    // gather K_sel / V_sel (32 rows x 64) into shared
    #pragma unroll
    for (int r = 0; r < 2; r++) {
        int lin = t + r*256;             // 512 float4 slots
        int row = lin >> 4, c4 = lin & 15;
        int ki = s_top[row];
        float4 kv = *(const float4*)(keys   + (size_t)((n*SQ + ki)*HH + h)*EE + c4*4);
        float4 vv = *(const float4*)(values + (size_t)((n*SQ + ki)*HH + h)*DD + c4*4);
        Ksel[row][c4*4+0] = kv.x; Ksel[row][c4*4+1] = kv.y;
        Ksel[row][c4*4+2] = kv.z; Ksel[row][c4*4+3] = kv.w;
        Vsel[row][c4*4+0] = vv.x; Vsel[row][c4*4+1] = vv.y;
        Vsel[row][c4*4+2] = vv.z; Vsel[row][c4*4+3] = vv.w;
    }
    __syncthreads();

    const float Ab = __ldg(&g_Ab[b]);
    const float vb0 = __ldg(&g_Vbtm[b*DD + lane]);
    const float vb1 = __ldg(&g_Vbtm[b*DD + lane + 32]);

    // warp-per-query; lane <-> key for QK, lane <-> d for AV
    for (int qi = q0 + wi; qi < q1; qi += 8) {
        const int l = g_qlist[qi];
        const float* qrow = q + (size_t)((n*LQ + l)*HH + h)*EE;
        const float qv0 = __ldg(qrow + lane);
        const float qv1 = __ldg(qrow + lane + 32);

        float dot = 0.f;
        #pragma unroll
        for (int e = 0; e < 32; e++) {
            float qe = __shfl_sync(~0u, qv0, e);
            dot += qe * Ksel[lane][e];
        }
        #pragma unroll
        for (int e = 0; e < 32; e++) {
            float qe = __shfl_sync(~0u, qv1, e);
            dot += qe * Ksel[lane][e + 32];
        }
        float lg = TEMP * dot;
        float m = lg;
        #pragma unroll
        for (int o = 16; o; o >>= 1) m = fmaxf(m, __shfl_xor_sync(~0u, m, o));
        float p = __expf(lg - m);
        float z = p;
        #pragma unroll
        for (int o = 16; o; o >>= 1) z += __shfl_xor_sync(~0u, z, o);
        const float wk = p * (Ab * __frcp_rn(z));

        float acc0 = vb0, acc1 = vb1;
        #pragma unroll
        for (int k = 0; k < KK; k++) {
            float wv = __shfl_sync(~0u, wk, k);
            acc0 += wv * Vsel[k][lane];
            acc1 += wv * Vsel[k][lane + 32];
        }
        float* orow = out + (size_t)((n*LQ + l)*HH + h)*DD;
        orow[lane]      = acc0;
        orow[lane + 32] = acc1;
    }
}

// ---------------- launch -----------------------------------------------------
extern "C" void kernel_launch(void* const* d_in, const int* in_sizes, int n_in,
                              void* d_out, int out_size) {
    const float* queries = (const float*)d_in[0];
    const float* keys    = (const float*)d_in[1];
    const float* values  = (const float*)d_in[2];
    const int*   cids    = (const int*)d_in[3];
    float* out = (float*)d_out;

    k_zero<<<(NH*CC*EE + 255)/256, 256>>>();
    k_qsum<<<(NB*HH*LQ*16 + 255)/256, 256>>>(queries, cids);
    k_qmean<<<(NH*CC*EE + 255)/256, 256>>>();
    k_scan<<<1, 1024>>>();
    k_scatter<<<(NH*LQ + 255)/256, 256>>>(cids);

    dim3 gB(SQ/64, CC/64, NH);
    k_qk<<<gB, 256>>>(keys);

    k_stats<<<NH*CC, 256>>>();

    dim3 gD(8, CC/64, NH);
    k_vbtm<<<gD, 256>>>(values);

    k_final2<<<NH*CC, 256>>>(queries, keys, values, out);
}

// round 6
// speedup vs baseline: 1.1615x; 1.0348x over previous
#include <cuda_runtime.h>
#include <math.h>

#define NB 2
#define LQ 2048
#define SQ 2048
#define HH 8
#define EE 64
#define DD 64
#define CC 256
#define KK 32
#define NH (NB*HH)
#define TEMP 0.125f

// ---------------- scratch (device globals; no allocation allowed) ----------
__device__ float g_Qg[NH*CC*EE];        // per-cluster mean queries
__device__ int   g_qcnt[NH*CC];         // cluster counts (int)
__device__ float g_probs[NH*CC*SQ];     // scores, then softmax probs (topk zeroed)
__device__ float g_Vbtm[NH*CC*DD];      // bottom-k weighted V per cluster
__device__ float g_Ab[NH*CC];           // top-k probability mass (= 1 - A_bottomk)
__device__ int   g_topk[NH*CC*KK];      // top-k key indices per cluster
__device__ int   g_qoff[NH*CC + 1];     // query-list offsets per cluster
__device__ int   g_qcur[NH*CC];         // scatter cursors
__device__ int   g_qlist[NH*LQ];        // query l-indices grouped by cluster

// ---------------- zero scratch ---------------------------------------------
__global__ void k_zero() {
    int i = blockIdx.x * blockDim.x + threadIdx.x;
    if (i < NH*CC*EE) { g_Qg[i] = 0.f; g_Vbtm[i] = 0.f; }
    if (i < NH*CC)    g_qcnt[i] = 0;
}

// ---------------- cluster sums via atomics ----------------------------------
__global__ void k_qsum(const float* __restrict__ q, const int* __restrict__ cid) {
    int t = blockIdx.x * blockDim.x + threadIdx.x;   // NB*HH*LQ*16 threads
    if (t >= NB*HH*LQ*16) return;
    int e4  = t & 15;
    int nhl = t >> 4;
    int l = nhl % LQ;
    int h = (nhl / LQ) % HH;
    int n = nhl / (LQ*HH);
    int c = __ldg(&cid[(n*HH + h)*LQ + l]);
    const float4 v = *(const float4*)(q + (size_t)((n*LQ + l)*HH + h)*EE + e4*4);
    float* dst = g_Qg + ((n*HH + h)*CC + c)*EE + e4*4;
    atomicAdd(dst + 0, v.x);
    atomicAdd(dst + 1, v.y);
    atomicAdd(dst + 2, v.z);
    atomicAdd(dst + 3, v.w);
    if (e4 == 0) atomicAdd(&g_qcnt[(n*HH + h)*CC + c], 1);
}

// ---------------- divide by counts + scan (block 1024) -----------------------
__global__ void k_meanscan() {
    if (blockIdx.x < 1024) {
        int i = blockIdx.x * blockDim.x + threadIdx.x;   // < NH*CC*EE
        g_Qg[i] /= fmaxf((float)g_qcnt[i >> 6], 1.f);
        return;
    }
    // block 1024: exclusive scan of 4096 counts with 256 threads x 16 items
    __shared__ int wsum[8];
    const int t = threadIdx.x, lane = t & 31, wid = t >> 5;
    int c[16], tot = 0;
    #pragma unroll
    for (int j = 0; j < 16; j++) { c[j] = g_qcnt[t*16 + j]; tot += c[j]; }
    int inc = tot;
    #pragma unroll
    for (int o = 1; o < 32; o <<= 1) {
        int x = __shfl_up_sync(~0u, inc, o);
        if (lane >= o) inc += x;
    }
    if (lane == 31) wsum[wid] = inc;
    __syncthreads();
    if (t < 8) {
        int v = wsum[t];
        #pragma unroll
        for (int o = 1; o < 8; o <<= 1) {
            int x = __shfl_up_sync(0xffu, v, o);
            if (t >= o) v += x;
        }
        wsum[t] = v;
    }
    __syncthreads();
    int ex = (wid ? wsum[wid-1] : 0) + inc - tot;
    #pragma unroll
    for (int j = 0; j < 16; j++) {
        g_qoff[t*16 + j] = ex;
        g_qcur[t*16 + j] = ex;
        ex += c[j];
    }
    if (t == 255) g_qoff[NH*CC] = ex;
}

// ---------------- scatter query indices into cluster-grouped lists ----------
__global__ void k_scatter(const int* __restrict__ cid) {
    int t = blockIdx.x * blockDim.x + threadIdx.x;   // NH*LQ threads
    if (t >= NH*LQ) return;
    int l  = t % LQ;
    int nh = t / LQ;
    int c  = __ldg(&cid[nh*LQ + l]);
    int pos = atomicAdd(&g_qcur[nh*CC + c], 1);
    g_qlist[pos] = l;
}

// ---------------- QK GEMM: scores[nh][c][s] = Qg[c]·K[s] --------------------
// strided 4x4 micro-tiles: rows tc+i*16, cols ts+j*16 (conflict-free LDS)
__global__ void k_qk(const float* __restrict__ keys) {
    __shared__ float shQ[64][65];
    __shared__ float shK[64][65];
    const int nh = blockIdx.z, n = nh >> 3, h = nh & 7;
    const int c0 = blockIdx.y * 64, s0 = blockIdx.x * 64;
    const int t = threadIdx.x;

    const float* Qb = g_Qg + (nh*CC + c0)*EE;
    #pragma unroll
    for (int r = 0; r < 4; r++) {
        int lin = t + r*256, row = lin >> 4, c4 = lin & 15;
        float4 v = *(const float4*)(Qb + row*EE + c4*4);
        shQ[row][c4*4+0] = v.x; shQ[row][c4*4+1] = v.y;
        shQ[row][c4*4+2] = v.z; shQ[row][c4*4+3] = v.w;
    }
    #pragma unroll
    for (int r = 0; r < 4; r++) {
        int lin = t + r*256, row = lin >> 4, c4 = lin & 15;
        float4 v = *(const float4*)(keys + (size_t)((n*SQ + s0 + row)*HH + h)*EE + c4*4);
        shK[row][c4*4+0] = v.x; shK[row][c4*4+1] = v.y;
        shK[row][c4*4+2] = v.z; shK[row][c4*4+3] = v.w;
    }
    __syncthreads();

    const int tc = t >> 4, ts = t & 15;
    float acc[4][4];
    #pragma unroll
    for (int i = 0; i < 4; i++)
        #pragma unroll
        for (int j = 0; j < 4; j++) acc[i][j] = 0.f;

    #pragma unroll 8
    for (int e = 0; e < 64; e++) {
        float a[4], b[4];
        #pragma unroll
        for (int i = 0; i < 4; i++) a[i] = shQ[tc + i*16][e];   // broadcast
        #pragma unroll
        for (int j = 0; j < 4; j++) b[j] = shK[ts + j*16][e];   // conflict-free
        #pragma unroll
        for (int i = 0; i < 4; i++)
            #pragma unroll
            for (int j = 0; j < 4; j++) acc[i][j] += a[i]*b[j];
    }
    #pragma unroll
    for (int i = 0; i < 4; i++) {
        float* dst = g_probs + (size_t)(nh*CC + c0 + tc + i*16)*SQ + s0 + ts;
        #pragma unroll
        for (int j = 0; j < 4; j++) dst[j*16] = acc[i][j];
    }
}

// ---------------- softmax + top-32 (register-resident) ----------------------
// one block (256 threads) per (nh, c) row of 2048 scores
__global__ void k_stats() {
    __shared__ float swv[8];
    __shared__ int   swi[8];
    const int row = blockIdx.x;
    const int t = threadIdx.x, lane = t & 31, wid = t >> 5;
    float* P = g_probs + (size_t)row * SQ;

    // load logits into registers, compute row max
    float v[8];
    float lmax = -INFINITY;
    #pragma unroll
    for (int j = 0; j < 8; j++) {
        v[j] = TEMP * P[t + j*256];
        lmax = fmaxf(lmax, v[j]);
    }
    #pragma unroll
    for (int o = 16; o; o >>= 1) lmax = fmaxf(lmax, __shfl_xor_sync(~0u, lmax, o));
    if (lane == 0) swv[wid] = lmax;
    __syncthreads();
    float M = swv[0];
    #pragma unroll
    for (int w = 1; w < 8; w++) M = fmaxf(M, swv[w]);
    __syncthreads();

    // denominator; cache exponentials for the prob-write
    float ex[8];
    float lsum = 0.f;
    #pragma unroll
    for (int j = 0; j < 8; j++) { ex[j] = __expf(v[j] - M); lsum += ex[j]; }
    #pragma unroll
    for (int o = 16; o; o >>= 1) lsum += __shfl_xor_sync(~0u, lsum, o);
    if (lane == 0) swv[wid] = lsum;
    __syncthreads();
    float Z = 0.f;
    #pragma unroll
    for (int w = 0; w < 8; w++) Z += swv[w];
    const float invZ = 1.f / Z;
    __syncthreads();

    // write normalized probs
    #pragma unroll
    for (int j = 0; j < 8; j++) P[t + j*256] = ex[j] * invZ;

    // iterative top-32: thread-local register argmax, warp shuffle, block scan
    float psum = 0.f;
    for (int it = 0; it < KK; it++) {
        float bv = -INFINITY; int bi = 0x7fffffff;
        #pragma unroll
        for (int j = 0; j < 8; j++) {
            // ascending j => ascending idx within thread; strict > keeps lowest idx
            if (v[j] > bv) { bv = v[j]; bi = t + j*256; }
        }
        #pragma unroll
        for (int o = 16; o; o >>= 1) {
            float ov = __shfl_xor_sync(~0u, bv, o);
            int   oi = __shfl_xor_sync(~0u, bi, o);
            if (ov > bv || (ov == bv && oi < bi)) { bv = ov; bi = oi; }
        }
        if (lane == 0) { swv[wid] = bv; swi[wid] = bi; }
        __syncthreads();
        float Bv = swv[0]; int Bi = swi[0];
        #pragma unroll
        for (int w = 1; w < 8; w++)
            if (swv[w] > Bv || (swv[w] == Bv && swi[w] < Bi)) { Bv = swv[w]; Bi = swi[w]; }
        psum += __expf(Bv - M);
        if (t == 0) g_topk[row*KK + it] = Bi;
        if ((Bi & 255) == t) {        // owner removes + zeroes prob
            v[Bi >> 8] = -INFINITY;
            P[Bi] = 0.f;
        }
        __syncthreads();
    }
    if (t == 0) g_Ab[row] = psum * invZ;   // top-k probability mass
}

// ---------------- V_btm = probs @ V (split-K, atomic accumulate) ------------
// strided 4x4 micro-tiles like k_qk
__global__ void k_vbtm(const float* __restrict__ values) {
    __shared__ float shP[64][33];
    __shared__ float shV[32][65];
    const int nh = blockIdx.z, n = nh >> 3, h = nh & 7;
    const int c0 = blockIdx.y * 64;
    const int sbase = blockIdx.x * 256;
    const int t = threadIdx.x;
    const int tc = t >> 4, ts = t & 15;

    float acc[4][4];
    #pragma unroll
    for (int i = 0; i < 4; i++)
        #pragma unroll
        for (int j = 0; j < 4; j++) acc[i][j] = 0.f;

    for (int ks = 0; ks < 8; ks++) {
        const int s0 = sbase + ks*32;
        #pragma unroll
        for (int r = 0; r < 2; r++) {
            int lin = t + r*256, row = lin >> 3, c4 = lin & 7;
            float4 v = *(const float4*)(g_probs + (size_t)(nh*CC + c0 + row)*SQ + s0 + c4*4);
            shP[row][c4*4+0] = v.x; shP[row][c4*4+1] = v.y;
            shP[row][c4*4+2] = v.z; shP[row][c4*4+3] = v.w;
        }
        #pragma unroll
        for (int r = 0; r < 2; r++) {
            int lin = t + r*256, row = lin >> 4, c4 = lin & 15;
            float4 v = *(const float4*)(values + (size_t)((n*SQ + s0 + row)*HH + h)*DD + c4*4);
            shV[row][c4*4+0] = v.x; shV[row][c4*4+1] = v.y;
            shV[row][c4*4+2] = v.z; shV[row][c4*4+3] = v.w;
        }
        __syncthreads();
        #pragma unroll 8
        for (int s = 0; s < 32; s++) {
            float a[4], b[4];
            #pragma unroll
            for (int i = 0; i < 4; i++) a[i] = shP[tc + i*16][s];    // broadcast
            #pragma unroll
            for (int j = 0; j < 4; j++) b[j] = shV[s][ts + j*16];    // conflict-free
            #pragma unroll
            for (int i = 0; i < 4; i++)
                #pragma unroll
                for (int j = 0; j < 4; j++) acc[i][j] += a[i]*b[j];
        }
        __syncthreads();
    }
    #pragma unroll
    for (int i = 0; i < 4; i++) {
        float* dst = g_Vbtm + (nh*CC + c0 + tc + i*16)*DD + ts;
        #pragma unroll
        for (int j = 0; j < 4; j++) atomicAdd(dst + j*16, acc[i][j]);
    }
}

// ---------------- per-cluster final attention --------------------------------
// one block per (nh, c): gather K_sel/V_sel once, serve all queries in cluster
__global__ void k_final2(const float* __restrict__ q, const float* __restrict__ keys,
                         const float* __restrict__ values, float* __restrict__ out) {
    __shared__ int   s_top[KK];
    __shared__ float Ksel[KK][65];
    __shared__ float Vsel[KK][65];
    const int b = blockIdx.x;            // nh*CC + c
    const int nh = b >> 8, n = nh >> 3, h = nh & 7;
    const int t = threadIdx.x, lane = t & 31, wi = t >> 5;

    const int q0 = g_qoff[b];
    const int q1 = g_qoff[b + 1];
    if (q0 == q1) return;                // empty cluster: nothing to emit

    if (t < KK) s_top[t] = g_topk[b*KK + t];
    __syncthreads();

    // gather K_sel / V_sel (32 rows x 64) into shared
    #pragma unroll
    for (int r = 0; r < 2; r++) {
        int lin = t + r*256;             // 512 float4 slots
        int row = lin >> 4, c4 = lin & 15;
        int ki = s_top[row];
        float4 kv = *(const float4*)(keys   + (size_t)((n*SQ + ki)*HH + h)*EE + c4*4);
        float4 vv = *(const float4*)(values + (size_t)((n*SQ + ki)*HH + h)*DD + c4*4);
        Ksel[row][c4*4+0] = kv.x; Ksel[row][c4*4+1] = kv.y;
        Ksel[row][c4*4+2] = kv.z; Ksel[row][c4*4+3] = kv.w;
        Vsel[row][c4*4+0] = vv.x; Vsel[row][c4*4+1] = vv.y;
        Vsel[row][c4*4+2] = vv.z; Vsel[row][c4*4+3] = vv.w;
    }
    __syncthreads();

    const float Ab = __ldg(&g_Ab[b]);
    const float vb0 = __ldg(&g_Vbtm[b*DD + lane]);
    const float vb1 = __ldg(&g_Vbtm[b*DD + lane + 32]);

    // warp-per-query; lane <-> key for QK, lane <-> d for AV
    for (int qi = q0 + wi; qi < q1; qi += 8) {
        const int l = g_qlist[qi];
        const float* qrow = q + (size_t)((n*LQ + l)*HH + h)*EE;
        const float qv0 = __ldg(qrow + lane);
        const float qv1 = __ldg(qrow + lane + 32);

        float dot = 0.f;
        #pragma unroll
        for (int e = 0; e < 32; e++) {
            float qe = __shfl_sync(~0u, qv0, e);
            dot += qe * Ksel[lane][e];
        }
        #pragma unroll
        for (int e = 0; e < 32; e++) {
            float qe = __shfl_sync(~0u, qv1, e);
            dot += qe * Ksel[lane][e + 32];
        }
        float lg = TEMP * dot;
        float m = lg;
        #pragma unroll
        for (int o = 16; o; o >>= 1) m = fmaxf(m, __shfl_xor_sync(~0u, m, o));
        float p = __expf(lg - m);
        float z = p;
        #pragma unroll
        for (int o = 16; o; o >>= 1) z += __shfl_xor_sync(~0u, z, o);
        const float wk = p * (Ab * __frcp_rn(z));

        float acc0 = vb0, acc1 = vb1;
        #pragma unroll
        for (int k = 0; k < KK; k++) {
            float wv = __shfl_sync(~0u, wk, k);
            acc0 += wv * Vsel[k][lane];
            acc1 += wv * Vsel[k][lane + 32];
        }
        float* orow = out + (size_t)((n*LQ + l)*HH + h)*DD;
        orow[lane]      = acc0;
        orow[lane + 32] = acc1;
    }
}

// ---------------- launch -----------------------------------------------------
extern "C" void kernel_launch(void* const* d_in, const int* in_sizes, int n_in,
                              void* d_out, int out_size) {
    const float* queries = (const float*)d_in[0];
    const float* keys    = (const float*)d_in[1];
    const float* values  = (const float*)d_in[2];
    const int*   cids    = (const int*)d_in[3];
    float* out = (float*)d_out;

    k_zero<<<(NH*CC*EE + 255)/256, 256>>>();
    k_qsum<<<(NB*HH*LQ*16 + 255)/256, 256>>>(queries, cids);
    k_meanscan<<<1025, 256>>>();
    k_scatter<<<(NH*LQ + 255)/256, 256>>>(cids);

    dim3 gB(SQ/64, CC/64, NH);
    k_qk<<<gB, 256>>>(keys);

    k_stats<<<NH*CC, 256>>>();

    dim3 gD(8, CC/64, NH);
    k_vbtm<<<gD, 256>>>(values);

    k_final2<<<NH*CC, 256>>>(queries, keys, values, out);
}

// round 7
// speedup vs baseline: 1.8218x; 1.5685x over previous
#include <cuda_runtime.h>
#include <math.h>

#define NB 2
#define LQ 2048
#define SQ 2048
#define HH 8
#define EE 64
#define DD 64
#define CC 256
#define KK 32
#define NH (NB*HH)
#define TEMP 0.125f
#define SCL 0.18033688011112042f   /* TEMP * log2(e) */

// ---------------- scratch (device globals; no allocation allowed) ----------
__device__ float g_Qg[NH*CC*EE];        // per-cluster mean queries
__device__ int   g_qcnt[NH*CC];         // cluster counts
__device__ float g_probs[NH*CC*SQ];     // scaled logits (log2 domain)
__device__ float g_Vbtm[NH*CC*DD];      // FULL softmax-weighted V per cluster
__device__ float g_Ab[NH*CC];           // top-k probability mass
__device__ float g_B[NH*CC];            // exp2 bias: log2(invZ) - M
__device__ int   g_topk[NH*CC*KK];      // top-k key indices per cluster
__device__ float g_topkp[NH*CC*KK];     // top-k probabilities per cluster
__device__ int   g_qoff[NH*CC + 1];     // query-list offsets per cluster
__device__ int   g_qcur[NH*CC];         // scatter cursors
__device__ int   g_qlist[NH*LQ];        // query l-indices grouped by cluster

// ---------------- zero scratch ---------------------------------------------
__global__ void k_zero() {
    int i = blockIdx.x * blockDim.x + threadIdx.x;
    if (i < NH*CC*EE) { g_Qg[i] = 0.f; g_Vbtm[i] = 0.f; }
    if (i < NH*CC)    g_qcnt[i] = 0;
}

// ---------------- cluster sums via atomics ----------------------------------
__global__ void k_qsum(const float* __restrict__ q, const int* __restrict__ cid) {
    int t = blockIdx.x * blockDim.x + threadIdx.x;   // NB*HH*LQ*16 threads
    if (t >= NB*HH*LQ*16) return;
    int e4  = t & 15;
    int nhl = t >> 4;
    int l = nhl % LQ;
    int h = (nhl / LQ) % HH;
    int n = nhl / (LQ*HH);
    int c = __ldg(&cid[(n*HH + h)*LQ + l]);
    const float4 v = *(const float4*)(q + (size_t)((n*LQ + l)*HH + h)*EE + e4*4);
    float* dst = g_Qg + ((n*HH + h)*CC + c)*EE + e4*4;
    atomicAdd(dst + 0, v.x);
    atomicAdd(dst + 1, v.y);
    atomicAdd(dst + 2, v.z);
    atomicAdd(dst + 3, v.w);
    if (e4 == 0) atomicAdd(&g_qcnt[(n*HH + h)*CC + c], 1);
}

// ---------------- divide by counts + scan (block 1024) -----------------------
__global__ void k_meanscan() {
    if (blockIdx.x < 1024) {
        int i = blockIdx.x * blockDim.x + threadIdx.x;
        g_Qg[i] /= fmaxf((float)g_qcnt[i >> 6], 1.f);
        return;
    }
    __shared__ int wsum[8];
    const int t = threadIdx.x, lane = t & 31, wid = t >> 5;
    int c[16], tot = 0;
    #pragma unroll
    for (int j = 0; j < 16; j++) { c[j] = g_qcnt[t*16 + j]; tot += c[j]; }
    int inc = tot;
    #pragma unroll
    for (int o = 1; o < 32; o <<= 1) {
        int x = __shfl_up_sync(~0u, inc, o);
        if (lane >= o) inc += x;
    }
    if (lane == 31) wsum[wid] = inc;
    __syncthreads();
    if (t < 8) {
        int v = wsum[t];
        #pragma unroll
        for (int o = 1; o < 8; o <<= 1) {
            int x = __shfl_up_sync(0xffu, v, o);
            if (t >= o) v += x;
        }
        wsum[t] = v;
    }
    __syncthreads();
    int ex = (wid ? wsum[wid-1] : 0) + inc - tot;
    #pragma unroll
    for (int j = 0; j < 16; j++) {
        g_qoff[t*16 + j] = ex;
        g_qcur[t*16 + j] = ex;
        ex += c[j];
    }
    if (t == 255) g_qoff[NH*CC] = ex;
}

// ---------------- scatter query indices into cluster-grouped lists ----------
__global__ void k_scatter(const int* __restrict__ cid) {
    int t = blockIdx.x * blockDim.x + threadIdx.x;
    if (t >= NH*LQ) return;
    int l  = t % LQ;
    int nh = t / LQ;
    int c  = __ldg(&cid[nh*LQ + l]);
    int pos = atomicAdd(&g_qcur[nh*CC + c], 1);
    g_qlist[pos] = l;
}

// ---------------- QK GEMM: swizzled float4 smem, contiguous 4x4 tiles -------
__global__ void k_qk(const float* __restrict__ keys) {
    __shared__ float4 shQ[64*16];
    __shared__ float4 shK[64*16];
    const int nh = blockIdx.z, n = nh >> 3, h = nh & 7;
    const int c0 = blockIdx.y * 64, s0 = blockIdx.x * 64;
    const int t = threadIdx.x;

    const float* Qb = g_Qg + (nh*CC + c0)*EE;
    #pragma unroll
    for (int r = 0; r < 4; r++) {
        int lin = t + r*256, row = lin >> 4, c4 = lin & 15;
        shQ[row*16 + (c4 ^ (row >> 2))] = *(const float4*)(Qb + row*EE + c4*4);
    }
    #pragma unroll
    for (int r = 0; r < 4; r++) {
        int lin = t + r*256, row = lin >> 4, c4 = lin & 15;
        shK[row*16 + (c4 ^ (row >> 2))] =
            *(const float4*)(keys + (size_t)((n*SQ + s0 + row)*HH + h)*EE + c4*4);
    }
    __syncthreads();

    const int tc = t >> 4, ts = t & 15;
    float acc[4][4];
    #pragma unroll
    for (int i = 0; i < 4; i++)
        #pragma unroll
        for (int j = 0; j < 4; j++) acc[i][j] = 0.f;

    #pragma unroll
    for (int e4 = 0; e4 < 16; e4++) {
        float4 a[4], b[4];
        #pragma unroll
        for (int i = 0; i < 4; i++) a[i] = shQ[(tc*4 + i)*16 + (e4 ^ tc)];
        #pragma unroll
        for (int j = 0; j < 4; j++) b[j] = shK[(ts*4 + j)*16 + (e4 ^ ts)];
        #pragma unroll
        for (int i = 0; i < 4; i++)
            #pragma unroll
            for (int j = 0; j < 4; j++)
                acc[i][j] += a[i].x*b[j].x + a[i].y*b[j].y + a[i].z*b[j].z + a[i].w*b[j].w;
    }
    #pragma unroll
    for (int i = 0; i < 4; i++) {
        float4 o;
        o.x = acc[i][0]*SCL; o.y = acc[i][1]*SCL; o.z = acc[i][2]*SCL; o.w = acc[i][3]*SCL;
        *(float4*)(g_probs + (size_t)(nh*CC + c0 + tc*4 + i)*SQ + s0 + ts*4) = o;
    }
}

// ---------------- softmax stats + top-32 (cached-best extraction) -----------
__global__ void k_stats() {
    __shared__ float    swf[8];
    __shared__ unsigned swu[8];
    __shared__ int      swi_[8];
    __shared__ unsigned s_bu;
    __shared__ int      s_bi;
    const int row = blockIdx.x;
    const int t = threadIdx.x, lane = t & 31, wid = t >> 5;
    const float* P = g_probs + (size_t)row * SQ;

    // load scaled logits (log2 domain), block max
    float v[8];
    float lmax = -INFINITY;
    #pragma unroll
    for (int j = 0; j < 8; j++) {
        v[j] = P[t + j*256];
        lmax = fmaxf(lmax, v[j]);
    }
    #pragma unroll
    for (int o = 16; o; o >>= 1) lmax = fmaxf(lmax, __shfl_xor_sync(~0u, lmax, o));
    if (lane == 0) swf[wid] = lmax;
    __syncthreads();
    float M = swf[0];
    #pragma unroll
    for (int w = 1; w < 8; w++) M = fmaxf(M, swf[w]);
    __syncthreads();

    // denominator
    float lsum = 0.f;
    #pragma unroll
    for (int j = 0; j < 8; j++) lsum += exp2f(v[j] - M);
    #pragma unroll
    for (int o = 16; o; o >>= 1) lsum += __shfl_xor_sync(~0u, lsum, o);
    if (lane == 0) swf[wid] = lsum;
    __syncthreads();
    float Z = 0.f;
    #pragma unroll
    for (int w = 0; w < 8; w++) Z += swf[w];
    const float invZ = 1.f / Z;

    // sortable keys
    unsigned u[8];
    #pragma unroll
    for (int j = 0; j < 8; j++) {
        unsigned b = __float_as_uint(v[j]);
        u[j] = (b & 0x80000000u) ? ~b : (b | 0x80000000u);
    }
    // cached local best (lowest idx among in-lane ties via strict >, ascending j)
    unsigned bu = 0u; int bj = 0;
    #pragma unroll
    for (int j = 0; j < 8; j++) if (u[j] > bu) { bu = u[j]; bj = j; }
    int bidx = t + bj*256;
    {
        unsigned mu = __reduce_max_sync(0xffffffffu, bu);
        unsigned cand = (bu == mu) ? (unsigned)bidx : 0xffffffffu;
        unsigned mi = __reduce_min_sync(0xffffffffu, cand);
        if (lane == 0) { swu[wid] = mu; swi_[wid] = (int)mi; }
    }
    __syncthreads();

    float psum = 0.f;
    for (int it = 0; it < KK; it++) {
        if (t == 0) {
            unsigned Bu = swu[0]; int Bi = swi_[0];
            #pragma unroll
            for (int w = 1; w < 8; w++)
                if (swu[w] > Bu || (swu[w] == Bu && swi_[w] < Bi)) { Bu = swu[w]; Bi = swi_[w]; }
            s_bu = Bu; s_bi = Bi;
            g_topk[row*KK + it] = Bi;
            unsigned fb = (Bu & 0x80000000u) ? (Bu & 0x7fffffffu) : ~Bu;
            float pv = exp2f(__uint_as_float(fb) - M);
            psum += pv;
            g_topkp[row*KK + it] = pv * invZ;
        }
        __syncthreads();
        const int Bi = s_bi;
        const int ot = Bi & 255;
        if (ot == t) {                   // owner thread: remove + rescan
            u[Bi >> 8] = 0u;
            bu = 0u; bj = 0;
            #pragma unroll
            for (int j = 0; j < 8; j++) if (u[j] > bu) { bu = u[j]; bj = j; }
            bidx = t + bj*256;
        }
        if ((ot >> 5) == wid) {          // owner warp: refresh its cached max
            unsigned mu = __reduce_max_sync(0xffffffffu, bu);
            unsigned cand = (bu == mu) ? (unsigned)bidx : 0xffffffffu;
            unsigned mi = __reduce_min_sync(0xffffffffu, cand);
            if (lane == 0) { swu[wid] = mu; swi_[wid] = (int)mi; }
        }
        __syncthreads();
    }
    if (t == 0) {
        g_Ab[row] = psum * invZ;
        g_B[row]  = log2f(invZ) - M;
    }
}

// ---------------- V_full = softmax @ V (split-K, atomic accumulate) ---------
__global__ void k_vbtm(const float* __restrict__ values) {
    __shared__ float shP[64][36];
    __shared__ float shV[32][68];
    __shared__ float sB[64];
    const int nh = blockIdx.z, n = nh >> 3, h = nh & 7;
    const int c0 = blockIdx.y * 64;
    const int sbase = blockIdx.x * 256;
    const int t = threadIdx.x;
    const int tc = t >> 4, ts = t & 15;

    if (t < 64) sB[t] = g_B[nh*CC + c0 + t];
    __syncthreads();

    float acc[4][4];
    #pragma unroll
    for (int i = 0; i < 4; i++)
        #pragma unroll
        for (int j = 0; j < 4; j++) acc[i][j] = 0.f;

    for (int ks = 0; ks < 8; ks++) {
        const int s0 = sbase + ks*32;
        #pragma unroll
        for (int r = 0; r < 2; r++) {
            int lin = t + r*256, row = lin >> 3, c4 = lin & 7;
            float4 v = *(const float4*)(g_probs + (size_t)(nh*CC + c0 + row)*SQ + s0 + c4*4);
            float bB = sB[row];
            float4 p;
            p.x = exp2f(v.x + bB); p.y = exp2f(v.y + bB);
            p.z = exp2f(v.z + bB); p.w = exp2f(v.w + bB);
            *(float4*)&shP[row][c4*4] = p;
        }
        #pragma unroll
        for (int r = 0; r < 2; r++) {
            int lin = t + r*256, row = lin >> 4, c4 = lin & 15;
            *(float4*)&shV[row][c4*4] =
                *(const float4*)(values + (size_t)((n*SQ + s0 + row)*HH + h)*DD + c4*4);
        }
        __syncthreads();
        #pragma unroll 8
        for (int s = 0; s < 32; s++) {
            float4 bv = *(const float4*)&shV[s][ts*4];
            #pragma unroll
            for (int i = 0; i < 4; i++) {
                float ai = shP[tc*4 + i][s];
                acc[i][0] += ai*bv.x; acc[i][1] += ai*bv.y;
                acc[i][2] += ai*bv.z; acc[i][3] += ai*bv.w;
            }
        }
        __syncthreads();
    }
    #pragma unroll
    for (int i = 0; i < 4; i++) {
        float* dst = g_Vbtm + (nh*CC + c0 + tc*4 + i)*DD + ts*4;
        #pragma unroll
        for (int j = 0; j < 4; j++) atomicAdd(dst + j, acc[i][j]);
    }
}

// ---------------- per-cluster final attention (with top-k correction) --------
__global__ void k_final2(const float* __restrict__ q, const float* __restrict__ keys,
                         const float* __restrict__ values, float* __restrict__ out) {
    __shared__ int   s_top[KK];
    __shared__ float s_ptp[KK];
    __shared__ float Ksel[KK][65];
    __shared__ float Vsel[KK][65];
    const int b = blockIdx.x;            // nh*CC + c
    const int nh = b >> 8, n = nh >> 3, h = nh & 7;
    const int t = threadIdx.x, lane = t & 31, wi = t >> 5;

    const int q0 = g_qoff[b];
    const int q1 = g_qoff[b + 1];
    if (q0 == q1) return;

    if (t < KK) { s_top[t] = g_topk[b*KK + t]; s_ptp[t] = g_topkp[b*KK + t]; }
    __syncthreads();

    #pragma unroll
    for (int r = 0; r < 2; r++) {
        int lin = t + r*256;
        int row = lin >> 4, c4 = lin & 15;
        int ki = s_top[row];
        float4 kv = *(const float4*)(keys   + (size_t)((n*SQ + ki)*HH + h)*EE + c4*4);
        float4 vv = *(const float4*)(values + (size_t)((n*SQ + ki)*HH + h)*DD + c4*4);
        Ksel[row][c4*4+0] = kv.x; Ksel[row][c4*4+1] = kv.y;
        Ksel[row][c4*4+2] = kv.z; Ksel[row][c4*4+3] = kv.w;
        Vsel[row][c4*4+0] = vv.x; Vsel[row][c4*4+1] = vv.y;
        Vsel[row][c4*4+2] = vv.z; Vsel[row][c4*4+3] = vv.w;
    }
    __syncthreads();

    const float Ab = __ldg(&g_Ab[b]);
    const float vb0 = __ldg(&g_Vbtm[b*DD + lane]);
    const float vb1 = __ldg(&g_Vbtm[b*DD + lane + 32]);

    for (int qi = q0 + wi; qi < q1; qi += 8) {
        const int l = g_qlist[qi];
        const float* qrow = q + (size_t)((n*LQ + l)*HH + h)*EE;
        const float qv0 = __ldg(qrow + lane);
        const float qv1 = __ldg(qrow + lane + 32);

        float dot = 0.f;
        #pragma unroll
        for (int e = 0; e < 32; e++) {
            float qe = __shfl_sync(~0u, qv0, e);
            dot += qe * Ksel[lane][e];
        }
        #pragma unroll
        for (int e = 0; e < 32; e++) {
            float qe = __shfl_sync(~0u, qv1, e);
            dot += qe * Ksel[lane][e + 32];
        }
        float lg = TEMP * dot;
        float m = lg;
        #pragma unroll
        for (int o = 16; o; o >>= 1) m = fmaxf(m, __shfl_xor_sync(~0u, m, o));
        float p = __expf(lg - m);
        float z = p;
        #pragma unroll
        for (int o = 16; o; o >>= 1) z += __shfl_xor_sync(~0u, z, o);
        const float wk = p * (Ab * __frcp_rn(z));

        // out = V_full + Σ_k (w_k − p_topk_k)·V_sel[k]
        float acc0 = vb0, acc1 = vb1;
        #pragma unroll
        for (int k = 0; k < KK; k++) {
            float wv = __shfl_sync(~0u, wk, k) - s_ptp[k];
            acc0 += wv * Vsel[k][lane];
            acc1 += wv * Vsel[k][lane + 32];
        }
        float* orow = out + (size_t)((n*LQ + l)*HH + h)*DD;
        orow[lane]      = acc0;
        orow[lane + 32] = acc1;
    }
}

// ---------------- launch -----------------------------------------------------
extern "C" void kernel_launch(void* const* d_in, const int* in_sizes, int n_in,
                              void* d_out, int out_size) {
    const float* queries = (const float*)d_in[0];
    const float* keys    = (const float*)d_in[1];
    const float* values  = (const float*)d_in[2];
    const int*   cids    = (const int*)d_in[3];
    float* out = (float*)d_out;

    k_zero<<<(NH*CC*EE + 255)/256, 256>>>();
    k_qsum<<<(NB*HH*LQ*16 + 255)/256, 256>>>(queries, cids);
    k_meanscan<<<1025, 256>>>();
    k_scatter<<<(NH*LQ + 255)/256, 256>>>(cids);

    dim3 gB(SQ/64, CC/64, NH);
    k_qk<<<gB, 256>>>(keys);

    k_stats<<<NH*CC, 256>>>();

    dim3 gD(8, CC/64, NH);
    k_vbtm<<<gD, 256>>>(values);

    k_final2<<<NH*CC, 256>>>(queries, keys, values, out);
}

// round 8
// speedup vs baseline: 1.8420x; 1.0111x over previous
#include <cuda_runtime.h>
#include <math.h>

#define NB 2
#define LQ 2048
#define SQ 2048
#define HH 8
#define EE 64
#define DD 64
#define CC 256
#define KK 32
#define NH (NB*HH)
#define TEMP 0.125f
#define SCL 0.18033688011112042f   /* TEMP * log2(e) */

// ---------------- scratch (device globals; no allocation allowed) ----------
__device__ float g_Qg[NH*CC*EE];        // per-cluster mean queries
__device__ int   g_qcnt[NH*CC];         // cluster counts
__device__ float g_probs[NH*CC*SQ];     // scaled logits (log2 domain, no max-shift)
__device__ float g_Vbtm[NH*CC*DD];      // FULL softmax-weighted V per cluster
__device__ float g_Ab[NH*CC];           // top-k probability mass
__device__ float g_B[NH*CC];            // exp2 bias: log2(invZ)
__device__ int   g_topk[NH*CC*KK];      // top-k key indices per cluster
__device__ float g_topkp[NH*CC*KK];     // top-k probabilities per cluster
__device__ int   g_qoff[NH*CC + 1];     // query-list offsets per cluster
__device__ int   g_qcur[NH*CC];         // scatter cursors
__device__ int   g_qlist[NH*LQ];        // query l-indices grouped by cluster

// ---------------- zero Vbtm + counts ----------------------------------------
__global__ void k_zero() {
    int i = blockIdx.x * blockDim.x + threadIdx.x;   // NH*CC*DD threads
    g_Vbtm[i] = 0.f;
    if (i < NH*CC) g_qcnt[i] = 0;
}

// ---------------- count queries per cluster ---------------------------------
__global__ void k_count(const int* __restrict__ cid) {
    int t = blockIdx.x * blockDim.x + threadIdx.x;   // NH*LQ threads
    if (t >= NH*LQ) return;
    atomicAdd(&g_qcnt[(t / LQ)*CC + __ldg(&cid[t])], 1);
}

// ---------------- exclusive scan of 4096 counts (1 block, 256 thr) ----------
__global__ void k_scan() {
    __shared__ int wsum[8];
    const int t = threadIdx.x, lane = t & 31, wid = t >> 5;
    int c[16], tot = 0;
    #pragma unroll
    for (int j = 0; j < 16; j++) { c[j] = g_qcnt[t*16 + j]; tot += c[j]; }
    int inc = tot;
    #pragma unroll
    for (int o = 1; o < 32; o <<= 1) {
        int x = __shfl_up_sync(~0u, inc, o);
        if (lane >= o) inc += x;
    }
    if (lane == 31) wsum[wid] = inc;
    __syncthreads();
    if (t < 8) {
        int v = wsum[t];
        #pragma unroll
        for (int o = 1; o < 8; o <<= 1) {
            int x = __shfl_up_sync(0xffu, v, o);
            if (t >= o) v += x;
        }
        wsum[t] = v;
    }
    __syncthreads();
    int ex = (wid ? wsum[wid-1] : 0) + inc - tot;
    #pragma unroll
    for (int j = 0; j < 16; j++) {
        g_qoff[t*16 + j] = ex;
        g_qcur[t*16 + j] = ex;
        ex += c[j];
    }
    if (t == 255) g_qoff[NH*CC] = ex;
}

// ---------------- scatter query indices into cluster-grouped lists ----------
__global__ void k_scatter(const int* __restrict__ cid) {
    int t = blockIdx.x * blockDim.x + threadIdx.x;
    if (t >= NH*LQ) return;
    int l  = t % LQ;
    int nh = t / LQ;
    int c  = __ldg(&cid[nh*LQ + l]);
    int pos = atomicAdd(&g_qcur[nh*CC + c], 1);
    g_qlist[pos] = l;
}

// ---------------- per-cluster query mean (warp per cluster, no atomics) -----
__global__ void k_qg(const float* __restrict__ q) {
    const int b = blockIdx.x*8 + (threadIdx.x >> 5);  // nh*CC + c
    const int lane = threadIdx.x & 31;
    const int nh = b >> 8, n = nh >> 3, h = nh & 7;
    const int q0 = g_qoff[b], q1 = g_qoff[b + 1];
    float a0 = 0.f, a1 = 0.f;
    for (int qi = q0; qi < q1; qi++) {
        const int l = g_qlist[qi];
        const float* qr = q + (size_t)((n*LQ + l)*HH + h)*EE;
        a0 += __ldg(qr + lane);
        a1 += __ldg(qr + lane + 32);
    }
    const float inv = 1.f / fmaxf((float)(q1 - q0), 1.f);
    g_Qg[b*EE + lane]      = a0 * inv;
    g_Qg[b*EE + lane + 32] = a1 * inv;
}

// ---------------- QK GEMM: 64x128 tile, 4x8 micro-tiles ---------------------
__global__ void k_qk(const float* __restrict__ keys) {
    __shared__ float4 shQ[64*16];
    __shared__ float4 shK[128*16];
    const int nh = blockIdx.z, n = nh >> 3, h = nh & 7;
    const int c0 = blockIdx.y * 64, s0 = blockIdx.x * 128;
    const int t = threadIdx.x;

    const float* Qb = g_Qg + (nh*CC + c0)*EE;
    #pragma unroll
    for (int r = 0; r < 4; r++) {
        int lin = t + r*256, row = lin >> 4, c4 = lin & 15;
        shQ[row*16 + c4] = *(const float4*)(Qb + row*EE + c4*4);
    }
    #pragma unroll
    for (int r = 0; r < 8; r++) {
        int lin = t + r*256, row = lin >> 4, c4 = lin & 15;
        shK[row*16 + (c4 ^ (row >> 3))] =
            *(const float4*)(keys + (size_t)((n*SQ + s0 + row)*HH + h)*EE + c4*4);
    }
    __syncthreads();

    const int tc = t >> 4, ts = t & 15;
    float acc[4][8];
    #pragma unroll
    for (int i = 0; i < 4; i++)
        #pragma unroll
        for (int j = 0; j < 8; j++) acc[i][j] = 0.f;

    #pragma unroll
    for (int e4 = 0; e4 < 16; e4++) {
        float4 a[4], b[8];
        #pragma unroll
        for (int i = 0; i < 4; i++) a[i] = shQ[(tc*4 + i)*16 + e4];       // broadcast
        #pragma unroll
        for (int j = 0; j < 8; j++) b[j] = shK[(ts*8 + j)*16 + (e4 ^ ts)]; // conflict-free
        #pragma unroll
        for (int i = 0; i < 4; i++)
            #pragma unroll
            for (int j = 0; j < 8; j++)
                acc[i][j] += a[i].x*b[j].x + a[i].y*b[j].y + a[i].z*b[j].z + a[i].w*b[j].w;
    }
    #pragma unroll
    for (int i = 0; i < 4; i++) {
        float* dst = g_probs + (size_t)(nh*CC + c0 + tc*4 + i)*SQ + s0 + ts*8;
        float4 o1, o2;
        o1.x = acc[i][0]*SCL; o1.y = acc[i][1]*SCL; o1.z = acc[i][2]*SCL; o1.w = acc[i][3]*SCL;
        o2.x = acc[i][4]*SCL; o2.y = acc[i][5]*SCL; o2.z = acc[i][6]*SCL; o2.w = acc[i][7]*SCL;
        *(float4*)dst       = o1;
        *(float4*)(dst + 4) = o2;
    }
}

// ---------------- softmax stats + top-32 (no max-shift, cached-best) --------
__global__ void k_stats() {
    __shared__ float    swf[8];
    __shared__ unsigned swu[8];
    __shared__ int      swi_[8];
    __shared__ unsigned s_bu;
    __shared__ int      s_bi;
    const int row = blockIdx.x;
    const int t = threadIdx.x, lane = t & 31, wid = t >> 5;
    const float* P = g_probs + (size_t)row * SQ;

    // load scaled logits; denominator (no max subtraction: |logit| small, fp32 safe)
    float v[8];
    float lsum = 0.f;
    #pragma unroll
    for (int j = 0; j < 8; j++) {
        v[j] = P[t + j*256];
        lsum += exp2f(v[j]);
    }
    #pragma unroll
    for (int o = 16; o; o >>= 1) lsum += __shfl_xor_sync(~0u, lsum, o);
    if (lane == 0) swf[wid] = lsum;
    __syncthreads();
    float Z = 0.f;
    #pragma unroll
    for (int w = 0; w < 8; w++) Z += swf[w];
    const float invZ = 1.f / Z;

    // sortable keys
    unsigned u[8];
    #pragma unroll
    for (int j = 0; j < 8; j++) {
        unsigned b = __float_as_uint(v[j]);
        u[j] = (b & 0x80000000u) ? ~b : (b | 0x80000000u);
    }
    // cached local best (lowest idx among in-lane ties via strict >, ascending j)
    unsigned bu = 0u; int bj = 0;
    #pragma unroll
    for (int j = 0; j < 8; j++) if (u[j] > bu) { bu = u[j]; bj = j; }
    int bidx = t + bj*256;
    {
        unsigned mu = __reduce_max_sync(0xffffffffu, bu);
        unsigned cand = (bu == mu) ? (unsigned)bidx : 0xffffffffu;
        unsigned mi = __reduce_min_sync(0xffffffffu, cand);
        if (lane == 0) { swu[wid] = mu; swi_[wid] = (int)mi; }
    }
    __syncthreads();

    float psum = 0.f;
    for (int it = 0; it < KK; it++) {
        if (t == 0) {
            unsigned Bu = swu[0]; int Bi = swi_[0];
            #pragma unroll
            for (int w = 1; w < 8; w++)
                if (swu[w] > Bu || (swu[w] == Bu && swi_[w] < Bi)) { Bu = swu[w]; Bi = swi_[w]; }
            s_bu = Bu; s_bi = Bi;
            g_topk[row*KK + it] = Bi;
            unsigned fb = (Bu & 0x80000000u) ? (Bu & 0x7fffffffu) : ~Bu;
            float pv = exp2f(__uint_as_float(fb));
            psum += pv;
            g_topkp[row*KK + it] = pv * invZ;
        }
        __syncthreads();
        const int Bi = s_bi;
        const int ot = Bi & 255;
        if (ot == t) {                   // owner thread: remove + rescan
            u[Bi >> 8] = 0u;
            bu = 0u; bj = 0;
            #pragma unroll
            for (int j = 0; j < 8; j++) if (u[j] > bu) { bu = u[j]; bj = j; }
            bidx = t + bj*256;
        }
        if ((ot >> 5) == wid) {          // owner warp: refresh its cached max
            unsigned mu = __reduce_max_sync(0xffffffffu, bu);
            unsigned cand = (bu == mu) ? (unsigned)bidx : 0xffffffffu;
            unsigned mi = __reduce_min_sync(0xffffffffu, cand);
            if (lane == 0) { swu[wid] = mu; swi_[wid] = (int)mi; }
        }
        __syncthreads();
    }
    if (t == 0) {
        g_Ab[row] = psum * invZ;
        g_B[row]  = log2f(invZ);
    }
}

// ---------------- V_full = softmax @ V (split-K, atomic accumulate) ---------
__global__ void k_vbtm(const float* __restrict__ values) {
    __shared__ float shP[64][36];
    __shared__ float shV[32][68];
    __shared__ float sB[64];
    const int nh = blockIdx.z, n = nh >> 3, h = nh & 7;
    const int c0 = blockIdx.y * 64;
    const int sbase = blockIdx.x * 256;
    const int t = threadIdx.x;
    const int tc = t >> 4, ts = t & 15;

    if (t < 64) sB[t] = g_B[nh*CC + c0 + t];
    __syncthreads();

    float acc[4][4];
    #pragma unroll
    for (int i = 0; i < 4; i++)
        #pragma unroll
        for (int j = 0; j < 4; j++) acc[i][j] = 0.f;

    for (int ks = 0; ks < 8; ks++) {
        const int s0 = sbase + ks*32;
        #pragma unroll
        for (int r = 0; r < 2; r++) {
            int lin = t + r*256, row = lin >> 3, c4 = lin & 7;
            float4 v = *(const float4*)(g_probs + (size_t)(nh*CC + c0 + row)*SQ + s0 + c4*4);
            float bB = sB[row];
            float4 p;
            p.x = exp2f(v.x + bB); p.y = exp2f(v.y + bB);
            p.z = exp2f(v.z + bB); p.w = exp2f(v.w + bB);
            *(float4*)&shP[row][c4*4] = p;
        }
        #pragma unroll
        for (int r = 0; r < 2; r++) {
            int lin = t + r*256, row = lin >> 4, c4 = lin & 15;
            *(float4*)&shV[row][c4*4] =
                *(const float4*)(values + (size_t)((n*SQ + s0 + row)*HH + h)*DD + c4*4);
        }
        __syncthreads();
        #pragma unroll 8
        for (int s = 0; s < 32; s++) {
            float4 bv = *(const float4*)&shV[s][ts*4];
            #pragma unroll
            for (int i = 0; i < 4; i++) {
                float ai = shP[tc*4 + i][s];
                acc[i][0] += ai*bv.x; acc[i][1] += ai*bv.y;
                acc[i][2] += ai*bv.z; acc[i][3] += ai*bv.w;
            }
        }
        __syncthreads();
    }
    #pragma unroll
    for (int i = 0; i < 4; i++) {
        float* dst = g_Vbtm + (nh*CC + c0 + tc*4 + i)*DD + ts*4;
        #pragma unroll
        for (int j = 0; j < 4; j++) atomicAdd(dst + j, acc[i][j]);
    }
}

// ---------------- per-cluster final attention (with top-k correction) --------
__global__ void k_final2(const float* __restrict__ q, const float* __restrict__ keys,
                         const float* __restrict__ values, float* __restrict__ out) {
    __shared__ int   s_top[KK];
    __shared__ float s_ptp[KK];
    __shared__ float Ksel[KK][65];
    __shared__ float Vsel[KK][65];
    const int b = blockIdx.x;            // nh*CC + c
    const int nh = b >> 8, n = nh >> 3, h = nh & 7;
    const int t = threadIdx.x, lane = t & 31, wi = t >> 5;

    const int q0 = g_qoff[b];
    const int q1 = g_qoff[b + 1];
    if (q0 == q1) return;

    if (t < KK) { s_top[t] = g_topk[b*KK + t]; s_ptp[t] = g_topkp[b*KK + t]; }
    __syncthreads();

    #pragma unroll
    for (int r = 0; r < 2; r++) {
        int lin = t + r*256;
        int row = lin >> 4, c4 = lin & 15;
        int ki = s_top[row];
        float4 kv = *(const float4*)(keys   + (size_t)((n*SQ + ki)*HH + h)*EE + c4*4);
        float4 vv = *(const float4*)(values + (size_t)((n*SQ + ki)*HH + h)*DD + c4*4);
        Ksel[row][c4*4+0] = kv.x; Ksel[row][c4*4+1] = kv.y;
        Ksel[row][c4*4+2] = kv.z; Ksel[row][c4*4+3] = kv.w;
        Vsel[row][c4*4+0] = vv.x; Vsel[row][c4*4+1] = vv.y;
        Vsel[row][c4*4+2] = vv.z; Vsel[row][c4*4+3] = vv.w;
    }
    __syncthreads();

    const float Ab = __ldg(&g_Ab[b]);
    const float vb0 = __ldg(&g_Vbtm[b*DD + lane]);
    const float vb1 = __ldg(&g_Vbtm[b*DD + lane + 32]);

    for (int qi = q0 + wi; qi < q1; qi += 8) {
        const int l = g_qlist[qi];
        const float* qrow = q + (size_t)((n*LQ + l)*HH + h)*EE;
        const float qv0 = __ldg(qrow + lane);
        const float qv1 = __ldg(qrow + lane + 32);

        float dot = 0.f;
        #pragma unroll
        for (int e = 0; e < 32; e++) {
            float qe = __shfl_sync(~0u, qv0, e);
            dot += qe * Ksel[lane][e];
        }
        #pragma unroll
        for (int e = 0; e < 32; e++) {
            float qe = __shfl_sync(~0u, qv1, e);
            dot += qe * Ksel[lane][e + 32];
        }
        float lg = TEMP * dot;
        float m = lg;
        #pragma unroll
        for (int o = 16; o; o >>= 1) m = fmaxf(m, __shfl_xor_sync(~0u, m, o));
        float p = __expf(lg - m);
        float z = p;
        #pragma unroll
        for (int o = 16; o; o >>= 1) z += __shfl_xor_sync(~0u, z, o);
        const float wk = p * (Ab * __frcp_rn(z));

        // out = V_full + Σ_k (w_k − p_topk_k)·V_sel[k]
        float acc0 = vb0, acc1 = vb1;
        #pragma unroll
        for (int k = 0; k < KK; k++) {
            float wv = __shfl_sync(~0u, wk, k) - s_ptp[k];
            acc0 += wv * Vsel[k][lane];
            acc1 += wv * Vsel[k][lane + 32];
        }
        float* orow = out + (size_t)((n*LQ + l)*HH + h)*DD;
        orow[lane]      = acc0;
        orow[lane + 32] = acc1;
    }
}

// ---------------- launch -----------------------------------------------------
extern "C" void kernel_launch(void* const* d_in, const int* in_sizes, int n_in,
                              void* d_out, int out_size) {
    const float* queries = (const float*)d_in[0];
    const float* keys    = (const float*)d_in[1];
    const float* values  = (const float*)d_in[2];
    const int*   cids    = (const int*)d_in[3];
    float* out = (float*)d_out;

    k_zero<<<NH*CC*DD/256, 256>>>();
    k_count<<<(NH*LQ + 255)/256, 256>>>(cids);
    k_scan<<<1, 256>>>();
    k_scatter<<<(NH*LQ + 255)/256, 256>>>(cids);
    k_qg<<<NH*CC/8, 256>>>(queries);

    dim3 gB(SQ/128, CC/64, NH);
    k_qk<<<gB, 256>>>(keys);

    k_stats<<<NH*CC, 256>>>();

    dim3 gD(8, CC/64, NH);
    k_vbtm<<<gD, 256>>>(values);

    k_final2<<<NH*CC, 256>>>(queries, keys, values, out);
}